// round 7
// baseline (speedup 1.0000x reference)
#include <cuda_runtime.h>
#include <math.h>

#define B_   8
#define C_   64
#define H_   256
#define W_   256
#define LD_  8
#define MEM_ 128
#define NROWS_ (B_ * W_)    // 2048
#define HCHUNK_ 64          // h rows per reduce/apply block
#define NQ_ (H_ / HCHUNK_)  // 4 chunks per plane
#define NBLK_ (B_ * C_ * NQ_)  // 2048
#define CQ_ (C_ * NQ_)      // 256 partial rows per batch
#define WSL_ 32             // w's per gate block
#define TPAD_ (CQ_ + 1)     // 257, conflict-free transpose stride

// Scratch (allocation-free per harness rules)
__device__ float g_part[NBLK_ * W_];     // partials, coalesced [bc*NQ+q][w] (2 MB)
__device__ float g_gateT[B_ * C_ * W_];  // gate*mu, [bc][w] (0.5 MB)

// ---------------------------------------------------------------------------
// Kernel 1: partial sum over a 64-row h-chunk of one (b,c) plane.
// Coalesced float4 partial store (no scatter tax on the read stream).
// ---------------------------------------------------------------------------
__global__ __launch_bounds__(256) void reduce_h_partial_kernel(const float* __restrict__ x) {
    const int bcq = blockIdx.x;           // 0 .. NBLK_-1  (= bc*4 + q)
    const int t  = threadIdx.x;
    const int w4 = t & 63;                // float4 column 0..63
    const int hs = t >> 6;                // h-subgroup 0..3

    const float4* __restrict__ xp =
        (const float4*)(x + (size_t)(bcq >> 2) * (H_ * W_) +
                        (size_t)(bcq & (NQ_ - 1)) * HCHUNK_ * W_);

    float4 s0 = make_float4(0.f, 0.f, 0.f, 0.f);
    float4 s1 = make_float4(0.f, 0.f, 0.f, 0.f);

#pragma unroll
    for (int half = 0; half < 2; ++half) {
        float4 v[8];
#pragma unroll
        for (int k = 0; k < 8; ++k)
            v[k] = xp[(size_t)(hs + 4 * (half * 8 + k)) * (W_ / 4) + w4];
#pragma unroll
        for (int k = 0; k < 8; ++k) {
            if (k & 1) { s1.x += v[k].x; s1.y += v[k].y; s1.z += v[k].z; s1.w += v[k].w; }
            else       { s0.x += v[k].x; s0.y += v[k].y; s0.z += v[k].z; s0.w += v[k].w; }
        }
    }
    float4 s = make_float4(s0.x + s1.x, s0.y + s1.y, s0.z + s1.z, s0.w + s1.w);

    __shared__ float4 red[256];
    red[t] = s;
    __syncthreads();
    if (hs == 0) {
        float4 a = red[t], b1 = red[t + 64], c1 = red[t + 128], d = red[t + 192];
        a.x += b1.x + c1.x + d.x;
        a.y += b1.y + c1.y + d.y;
        a.z += b1.z + c1.z + d.z;
        a.w += b1.w + c1.w + d.w;
        __stcs(&((float4*)g_part)[(size_t)bcq * (W_ / 4) + w4], a);   // coalesced
    }
}

// ---------------------------------------------------------------------------
// Kernel 2: gating MLP + memory-bank attention. 64 blocks; block covers
// (b, 32 consecutive w). Partial tile transposed through padded smem, then
// warp-per-row math (4 rows per warp sequentially).
// ---------------------------------------------------------------------------
__global__ __launch_bounds__(256) void gate_kernel(
    const float* __restrict__ w_sub, const float* __restrict__ b_sub,
    const float* __restrict__ w_up,  const float* __restrict__ b_up,
    const float* __restrict__ mb,    const float* __restrict__ mu)
{
    __shared__ float s_wsub[C_ * LD_];
    __shared__ float s_mb[LD_ * MEM_];
    __shared__ float s_wup[LD_ * C_];
    __shared__ float s_bsub[LD_];
    __shared__ float s_bup[C_];
    __shared__ float tileT[WSL_ * TPAD_];   // [wl][c*4+q], padded

    const int tid = threadIdx.x;
    for (int i = tid; i < C_ * LD_;   i += blockDim.x) s_wsub[i] = w_sub[i];
    for (int i = tid; i < LD_ * MEM_; i += blockDim.x) s_mb[i]   = mb[i];
    for (int i = tid; i < LD_ * C_;   i += blockDim.x) s_wup[i]  = w_up[i];
    if (tid < LD_) s_bsub[tid] = b_sub[tid];
    if (tid < C_)  s_bup[tid]  = b_up[tid];

    const int b  = blockIdx.x >> 3;            // batch
    const int ws = (blockIdx.x & 7) * WSL_;    // w slice start
    const int wp = tid >> 5;
    const int lane = tid & 31;

    // Stage + transpose: row r (= c*4+q) of this batch, columns ws..ws+31.
    // One 128B coalesced load per row; write stride TPAD_ -> conflict-free.
    for (int r = wp; r < CQ_; r += 8) {
        const float v = g_part[((size_t)b * CQ_ + r) * W_ + ws + lane];
        tileT[lane * TPAD_ + r] = v;
    }
    __syncthreads();

    const float muv  = mu[0];
    const float inv_h = 1.0f / H_;
    const float scale = rsqrtf((float)LD_);

    // Warp wp handles w-rows wl = wp*4 .. wp*4+3
#pragma unroll
    for (int it = 0; it < 4; ++it) {
        const int wl = wp * 4 + it;
        const int w  = ws + wl;

        // y[c] for c = lane and c = lane+32: 4 q-partials each, from smem
        const float* tr = tileT + wl * TPAD_;
        float yA = 0.f, yB = 0.f;
#pragma unroll
        for (int q = 0; q < NQ_; ++q) {
            yA += tr[lane * 4 + q];
            yB += tr[(lane + 32) * 4 + q];
        }
        yA *= inv_h; yB *= inv_h;

        float low[LD_];
#pragma unroll
        for (int j = 0; j < LD_; ++j) {
            float p = fmaf(yA, s_wsub[lane * LD_ + j],
                           yB * s_wsub[(lane + 32) * LD_ + j]);
#pragma unroll
            for (int off = 16; off > 0; off >>= 1)
                p += __shfl_xor_sync(0xffffffffu, p, off);
            low[j] = p + s_bsub[j];
        }

        float f1[4];
#pragma unroll
        for (int k = 0; k < 4; ++k) {
            const int m = lane + 32 * k;
            float acc = 0.f;
#pragma unroll
            for (int j = 0; j < LD_; ++j)
                acc = fmaf(low[j], s_mb[j * MEM_ + m], acc);
            f1[k] = acc * scale;
        }

        float mx = fmaxf(fmaxf(f1[0], f1[1]), fmaxf(f1[2], f1[3]));
#pragma unroll
        for (int off = 16; off > 0; off >>= 1)
            mx = fmaxf(mx, __shfl_xor_sync(0xffffffffu, mx, off));
        float e[4], sum = 0.f;
#pragma unroll
        for (int k = 0; k < 4; ++k) { e[k] = expf(f1[k] - mx); sum += e[k]; }
#pragma unroll
        for (int off = 16; off > 0; off >>= 1)
            sum += __shfl_xor_sync(0xffffffffu, sum, off);
        const float inv = 1.0f / sum;

        float y1[LD_];
#pragma unroll
        for (int j = 0; j < LD_; ++j) {
            float acc = 0.f;
#pragma unroll
            for (int k = 0; k < 4; ++k)
                acc = fmaf(e[k] * inv, s_mb[j * MEM_ + lane + 32 * k], acc);
#pragma unroll
            for (int off = 16; off > 0; off >>= 1)
                acc += __shfl_xor_sync(0xffffffffu, acc, off);
            y1[j] = acc;
        }

#pragma unroll
        for (int k = 0; k < 2; ++k) {
            const int c = lane + 32 * k;
            float acc = s_bup[c];
#pragma unroll
            for (int j = 0; j < LD_; ++j)
                acc = fmaf(y1[j], s_wup[j * C_ + c], acc);
            const float g = 1.0f / (1.0f + expf(-acc));
            g_gateT[(size_t)(b * C_ + c) * W_ + w] = g * muv;
        }
    }
}

// ---------------------------------------------------------------------------
// Kernel 3: out = x * gate. Thread's float4 column is fixed -> gate is one
// float4 register. Loads batched 8-deep; streaming stores; reverse block order.
// ---------------------------------------------------------------------------
__global__ __launch_bounds__(256) void apply_gate_kernel(
    const float* __restrict__ x, float* __restrict__ out)
{
    const int bcq = (NBLK_ - 1) - blockIdx.x;   // reverse order
    const int bc  = bcq >> 2;
    const int q   = bcq & (NQ_ - 1);

    const int t   = threadIdx.x;
    const int w4  = t & 63;
    const int hs  = t >> 6;

    const float4 gv = __ldg(&((const float4*)(g_gateT + (size_t)bc * W_))[w4]);

    const size_t base = (size_t)bc * (H_ * W_) + (size_t)q * HCHUNK_ * W_;
    const float4* __restrict__ xp = (const float4*)(x + base);
    float4*       __restrict__ op = (float4*)(out + base);

#pragma unroll
    for (int half = 0; half < 2; ++half) {
        float4 v[8];
#pragma unroll
        for (int k = 0; k < 8; ++k)
            v[k] = __ldcs(&xp[(size_t)(hs + 4 * (half * 8 + k)) * (W_ / 4) + w4]);
#pragma unroll
        for (int k = 0; k < 8; ++k) {
            v[k].x *= gv.x; v[k].y *= gv.y; v[k].z *= gv.z; v[k].w *= gv.w;
            __stcs(&op[(size_t)(hs + 4 * (half * 8 + k)) * (W_ / 4) + w4], v[k]);
        }
    }
}

extern "C" void kernel_launch(void* const* d_in, const int* in_sizes, int n_in,
                              void* d_out, int out_size) {
    const float* x     = (const float*)d_in[0];
    const float* w_sub = (const float*)d_in[1];
    const float* b_sub = (const float*)d_in[2];
    const float* w_up  = (const float*)d_in[3];
    const float* b_up  = (const float*)d_in[4];
    const float* mb    = (const float*)d_in[5];
    const float* mu    = (const float*)d_in[6];
    float* out = (float*)d_out;

    reduce_h_partial_kernel<<<NBLK_, 256>>>(x);
    gate_kernel<<<64, 256>>>(w_sub, b_sub, w_up, b_up, mb, mu);
    apply_gate_kernel<<<NBLK_, 256>>>(x, out);
}

// round 8
// speedup vs baseline: 1.0363x; 1.0363x over previous
#include <cuda_runtime.h>
#include <math.h>

#define B_   8
#define C_   64
#define H_   256
#define W_   256
#define LD_  8
#define MEM_ 128
#define NROWS_ (B_ * W_)    // 2048
#define HCHUNK_ 64          // h rows per reduce/apply block
#define NQ_ (H_ / HCHUNK_)  // 4 chunks per plane
#define NBLK_ (B_ * C_ * NQ_)  // 2048
#define CQ_ (C_ * NQ_)      // 256 partial rows per batch

// Scratch (allocation-free per harness rules)
__device__ float g_part[NBLK_ * W_];      // partials [b][c*4+q][w], coalesced (2 MB)
__device__ float g_partT[B_ * W_ * CQ_];  // transposed [b][w][c*4+q]        (2 MB)
__device__ float g_gateT[B_ * C_ * W_];   // gate*mu, [bc][w]                (0.5 MB)

// ---------------------------------------------------------------------------
// Kernel 1: partial sum over a 64-row h-chunk of one (b,c) plane.
// Coalesced float4 partial store — no scatter tax on the x read stream.
// ---------------------------------------------------------------------------
__global__ __launch_bounds__(256) void reduce_h_partial_kernel(const float* __restrict__ x) {
    const int bcq = blockIdx.x;           // = (b*C + c)*4 + q
    const int t  = threadIdx.x;
    const int w4 = t & 63;                // float4 column 0..63
    const int hs = t >> 6;                // h-subgroup 0..3

    const float4* __restrict__ xp =
        (const float4*)(x + (size_t)(bcq >> 2) * (H_ * W_) +
                        (size_t)(bcq & (NQ_ - 1)) * HCHUNK_ * W_);

    float4 s0 = make_float4(0.f, 0.f, 0.f, 0.f);
    float4 s1 = make_float4(0.f, 0.f, 0.f, 0.f);

#pragma unroll
    for (int half = 0; half < 2; ++half) {
        float4 v[8];
#pragma unroll
        for (int k = 0; k < 8; ++k)
            v[k] = xp[(size_t)(hs + 4 * (half * 8 + k)) * (W_ / 4) + w4];
#pragma unroll
        for (int k = 0; k < 8; ++k) {
            if (k & 1) { s1.x += v[k].x; s1.y += v[k].y; s1.z += v[k].z; s1.w += v[k].w; }
            else       { s0.x += v[k].x; s0.y += v[k].y; s0.z += v[k].z; s0.w += v[k].w; }
        }
    }
    float4 s = make_float4(s0.x + s1.x, s0.y + s1.y, s0.z + s1.z, s0.w + s1.w);

    __shared__ float4 red[256];
    red[t] = s;
    __syncthreads();
    if (hs == 0) {
        float4 a = red[t], b1 = red[t + 64], c1 = red[t + 128], d = red[t + 192];
        a.x += b1.x + c1.x + d.x;
        a.y += b1.y + c1.y + d.y;
        a.z += b1.z + c1.z + d.z;
        a.w += b1.w + c1.w + d.w;
        __stcs(&((float4*)g_part)[(size_t)bcq * (W_ / 4) + w4], a);   // coalesced
    }
}

// ---------------------------------------------------------------------------
// Kernel 1b: transpose partials per batch: [cq][w] -> [w][cq].
// 512 blocks; classic padded 32x32 smem tile, coalesced both directions.
// Data is L2-warm (just written by reduce).
// ---------------------------------------------------------------------------
__global__ __launch_bounds__(256) void transpose_part_kernel() {
    __shared__ float tile[32][33];
    const int b  = blockIdx.x >> 6;
    const int ti = (blockIdx.x >> 3) & 7;   // cq tile
    const int tj = blockIdx.x & 7;          // w  tile
    const int lx = threadIdx.x & 31;
    const int ly = threadIdx.x >> 5;        // 0..7

#pragma unroll
    for (int k = 0; k < 4; ++k) {
        const int cq = ti * 32 + ly + k * 8;
        tile[ly + k * 8][lx] = g_part[((size_t)b * CQ_ + cq) * W_ + tj * 32 + lx];
    }
    __syncthreads();
#pragma unroll
    for (int k = 0; k < 4; ++k) {
        const int w = tj * 32 + ly + k * 8;
        g_partT[((size_t)b * W_ + w) * CQ_ + ti * 32 + lx] = tile[lx][ly + k * 8];
    }
}

// ---------------------------------------------------------------------------
// Kernel 2: gating MLP + memory-bank attention. Warp per row (b,w).
// Partials read as 2 coalesced float4 loads per lane (L2 hits).
// ---------------------------------------------------------------------------
__global__ __launch_bounds__(256) void gate_kernel(
    const float* __restrict__ w_sub, const float* __restrict__ b_sub,
    const float* __restrict__ w_up,  const float* __restrict__ b_up,
    const float* __restrict__ mb,    const float* __restrict__ mu)
{
    __shared__ float s_wsub[C_ * LD_];
    __shared__ float s_mb[LD_ * MEM_];
    __shared__ float s_wup[LD_ * C_];
    __shared__ float s_bsub[LD_];
    __shared__ float s_bup[C_];

    const int tid = threadIdx.x;
    for (int i = tid; i < C_ * LD_;   i += blockDim.x) s_wsub[i] = w_sub[i];
    for (int i = tid; i < LD_ * MEM_; i += blockDim.x) s_mb[i]   = mb[i];
    for (int i = tid; i < LD_ * C_;   i += blockDim.x) s_wup[i]  = w_up[i];
    if (tid < LD_) s_bsub[tid] = b_sub[tid];
    if (tid < C_)  s_bup[tid]  = b_up[tid];
    __syncthreads();

    const float muv = mu[0];
    const int warp = tid >> 5;
    const int lane = tid & 31;
    const int row  = blockIdx.x * (blockDim.x >> 5) + warp;
    if (row >= NROWS_) return;

    const int b = row / W_;
    const int w = row % W_;

    // y[c] for c = lane, lane+32: one float4 (4 q-partials) each, coalesced.
    const float4* __restrict__ yp = (const float4*)(g_partT + (size_t)row * CQ_);
    const float4 pa = yp[lane];
    const float4 pb = yp[lane + 32];
    const float inv_h = 1.0f / H_;
    const float yA = (pa.x + pa.y + pa.z + pa.w) * inv_h;
    const float yB = (pb.x + pb.y + pb.z + pb.w) * inv_h;

    float low[LD_];
#pragma unroll
    for (int j = 0; j < LD_; ++j) {
        float p = fmaf(yA, s_wsub[lane * LD_ + j],
                       yB * s_wsub[(lane + 32) * LD_ + j]);
#pragma unroll
        for (int off = 16; off > 0; off >>= 1)
            p += __shfl_xor_sync(0xffffffffu, p, off);
        low[j] = p + s_bsub[j];
    }

    const float scale = rsqrtf((float)LD_);
    float f1[4];
#pragma unroll
    for (int k = 0; k < 4; ++k) {
        const int m = lane + 32 * k;
        float acc = 0.f;
#pragma unroll
        for (int j = 0; j < LD_; ++j)
            acc = fmaf(low[j], s_mb[j * MEM_ + m], acc);
        f1[k] = acc * scale;
    }

    float mx = fmaxf(fmaxf(f1[0], f1[1]), fmaxf(f1[2], f1[3]));
#pragma unroll
    for (int off = 16; off > 0; off >>= 1)
        mx = fmaxf(mx, __shfl_xor_sync(0xffffffffu, mx, off));
    float e[4], sum = 0.f;
#pragma unroll
    for (int k = 0; k < 4; ++k) { e[k] = expf(f1[k] - mx); sum += e[k]; }
#pragma unroll
    for (int off = 16; off > 0; off >>= 1)
        sum += __shfl_xor_sync(0xffffffffu, sum, off);
    const float inv = 1.0f / sum;

    float y1[LD_];
#pragma unroll
    for (int j = 0; j < LD_; ++j) {
        float acc = 0.f;
#pragma unroll
        for (int k = 0; k < 4; ++k)
            acc = fmaf(e[k] * inv, s_mb[j * MEM_ + lane + 32 * k], acc);
#pragma unroll
        for (int off = 16; off > 0; off >>= 1)
            acc += __shfl_xor_sync(0xffffffffu, acc, off);
        y1[j] = acc;
    }

#pragma unroll
    for (int k = 0; k < 2; ++k) {
        const int c = lane + 32 * k;
        float acc = s_bup[c];
#pragma unroll
        for (int j = 0; j < LD_; ++j)
            acc = fmaf(y1[j], s_wup[j * C_ + c], acc);
        const float g = 1.0f / (1.0f + expf(-acc));
        g_gateT[(size_t)(b * C_ + c) * W_ + w] = g * muv;
    }
}

// ---------------------------------------------------------------------------
// Kernel 3: out = x * gate. Thread's float4 column is fixed -> gate is one
// float4 register. Loads batched 8-deep; streaming stores; reverse block order.
// ---------------------------------------------------------------------------
__global__ __launch_bounds__(256) void apply_gate_kernel(
    const float* __restrict__ x, float* __restrict__ out)
{
    const int bcq = (NBLK_ - 1) - blockIdx.x;   // reverse order
    const int bc  = bcq >> 2;
    const int q   = bcq & (NQ_ - 1);

    const int t   = threadIdx.x;
    const int w4  = t & 63;
    const int hs  = t >> 6;

    const float4 gv = __ldg(&((const float4*)(g_gateT + (size_t)bc * W_))[w4]);

    const size_t base = (size_t)bc * (H_ * W_) + (size_t)q * HCHUNK_ * W_;
    const float4* __restrict__ xp = (const float4*)(x + base);
    float4*       __restrict__ op = (float4*)(out + base);

#pragma unroll
    for (int half = 0; half < 2; ++half) {
        float4 v[8];
#pragma unroll
        for (int k = 0; k < 8; ++k)
            v[k] = __ldcs(&xp[(size_t)(hs + 4 * (half * 8 + k)) * (W_ / 4) + w4]);
#pragma unroll
        for (int k = 0; k < 8; ++k) {
            v[k].x *= gv.x; v[k].y *= gv.y; v[k].z *= gv.z; v[k].w *= gv.w;
            __stcs(&op[(size_t)(hs + 4 * (half * 8 + k)) * (W_ / 4) + w4], v[k]);
        }
    }
}

extern "C" void kernel_launch(void* const* d_in, const int* in_sizes, int n_in,
                              void* d_out, int out_size) {
    const float* x     = (const float*)d_in[0];
    const float* w_sub = (const float*)d_in[1];
    const float* b_sub = (const float*)d_in[2];
    const float* w_up  = (const float*)d_in[3];
    const float* b_up  = (const float*)d_in[4];
    const float* mb    = (const float*)d_in[5];
    const float* mu    = (const float*)d_in[6];
    float* out = (float*)d_out;

    reduce_h_partial_kernel<<<NBLK_, 256>>>(x);
    transpose_part_kernel<<<512, 256>>>();
    gate_kernel<<<NROWS_ / 8, 256>>>(w_sub, b_sub, w_up, b_up, mb, mu);
    apply_gate_kernel<<<NBLK_, 256>>>(x, out);
}

// round 9
// speedup vs baseline: 1.0557x; 1.0187x over previous
#include <cuda_runtime.h>
#include <math.h>

#define B_   8
#define C_   64
#define H_   256
#define W_   256
#define LD_  8
#define MEM_ 128
#define NROWS_ (B_ * W_)    // 2048
#define HCHUNK_ 64          // h rows per reduce/apply block
#define NQ_ (H_ / HCHUNK_)  // 4 chunks per plane
#define NBLK_ (B_ * C_ * NQ_)  // 2048
#define CQ_ (C_ * NQ_)      // 256

// Scratch (allocation-free per harness rules)
// Partials transposed at the producer: [b][w][c][q] (2 MB). The 8 writers of
// each 32B sector merge in write-back L2 (verified R6).
__device__ float g_partT[B_ * W_ * C_ * NQ_];
__device__ float g_gateT[B_ * C_ * W_];       // gate*mu, [bc][w] (0.5 MB)

// ---------------------------------------------------------------------------
// Kernel 1: partial sum over a 64-row h-chunk of one (b,c) plane, with
// transposed scatter store (R6 form, measured 24.8us).
// ---------------------------------------------------------------------------
__global__ __launch_bounds__(256) void reduce_h_partial_kernel(const float* __restrict__ x) {
    const int bcq = blockIdx.x;           // = bc*4 + q
    const int bc  = bcq >> 2;
    const int q   = bcq & (NQ_ - 1);

    const int t  = threadIdx.x;
    const int w4 = t & 63;                // float4 column 0..63
    const int hs = t >> 6;                // h-subgroup 0..3

    const float4* __restrict__ xp =
        (const float4*)(x + (size_t)bc * (H_ * W_) + (size_t)q * HCHUNK_ * W_);

    float4 s0 = make_float4(0.f, 0.f, 0.f, 0.f);
    float4 s1 = make_float4(0.f, 0.f, 0.f, 0.f);

#pragma unroll
    for (int half = 0; half < 2; ++half) {
        float4 v[8];
#pragma unroll
        for (int k = 0; k < 8; ++k)
            v[k] = xp[(size_t)(hs + 4 * (half * 8 + k)) * (W_ / 4) + w4];
#pragma unroll
        for (int k = 0; k < 8; ++k) {
            if (k & 1) { s1.x += v[k].x; s1.y += v[k].y; s1.z += v[k].z; s1.w += v[k].w; }
            else       { s0.x += v[k].x; s0.y += v[k].y; s0.z += v[k].z; s0.w += v[k].w; }
        }
    }
    float4 s = make_float4(s0.x + s1.x, s0.y + s1.y, s0.z + s1.z, s0.w + s1.w);

    __shared__ float4 red[256];
    red[t] = s;
    __syncthreads();
    if (hs == 0) {
        float4 a = red[t], b1 = red[t + 64], c1 = red[t + 128], d = red[t + 192];
        a.x += b1.x + c1.x + d.x;
        a.y += b1.y + c1.y + d.y;
        a.z += b1.z + c1.z + d.z;
        a.w += b1.w + c1.w + d.w;

        const int b = bc / C_;
        const int c = bc % C_;
        const size_t stride = (size_t)C_ * NQ_;              // +1 in w
        size_t o = (((size_t)b * W_ + 4 * w4) * C_ + c) * NQ_ + q;
        g_partT[o]              = a.x;
        g_partT[o + stride]     = a.y;
        g_partT[o + 2 * stride] = a.z;
        g_partT[o + 3 * stride] = a.w;
    }
}

// ---------------------------------------------------------------------------
// Kernel 2: gating MLP + memory-bank attention. Warp per row (b,w).
// Partials read as 2 coalesced float4 loads per lane (L2 hits). (R6 form.)
// ---------------------------------------------------------------------------
__global__ __launch_bounds__(256) void gate_kernel(
    const float* __restrict__ w_sub, const float* __restrict__ b_sub,
    const float* __restrict__ w_up,  const float* __restrict__ b_up,
    const float* __restrict__ mb,    const float* __restrict__ mu)
{
    __shared__ float s_wsub[C_ * LD_];
    __shared__ float s_mb[LD_ * MEM_];
    __shared__ float s_wup[LD_ * C_];
    __shared__ float s_bsub[LD_];
    __shared__ float s_bup[C_];

    const int tid = threadIdx.x;
    for (int i = tid; i < C_ * LD_;   i += blockDim.x) s_wsub[i] = w_sub[i];
    for (int i = tid; i < LD_ * MEM_; i += blockDim.x) s_mb[i]   = mb[i];
    for (int i = tid; i < LD_ * C_;   i += blockDim.x) s_wup[i]  = w_up[i];
    if (tid < LD_) s_bsub[tid] = b_sub[tid];
    if (tid < C_)  s_bup[tid]  = b_up[tid];
    __syncthreads();

    const float muv = mu[0];
    const int warp = tid >> 5;
    const int lane = tid & 31;
    const int row  = blockIdx.x * (blockDim.x >> 5) + warp;
    if (row >= NROWS_) return;

    const int b = row / W_;
    const int w = row % W_;

    const float4* __restrict__ yp = (const float4*)(g_partT + (size_t)row * CQ_);
    const float4 pa = yp[lane];
    const float4 pb = yp[lane + 32];
    const float inv_h = 1.0f / H_;
    const float yA = (pa.x + pa.y + pa.z + pa.w) * inv_h;
    const float yB = (pb.x + pb.y + pb.z + pb.w) * inv_h;

    float low[LD_];
#pragma unroll
    for (int j = 0; j < LD_; ++j) {
        float p = fmaf(yA, s_wsub[lane * LD_ + j],
                       yB * s_wsub[(lane + 32) * LD_ + j]);
#pragma unroll
        for (int off = 16; off > 0; off >>= 1)
            p += __shfl_xor_sync(0xffffffffu, p, off);
        low[j] = p + s_bsub[j];
    }

    const float scale = rsqrtf((float)LD_);
    float f1[4];
#pragma unroll
    for (int k = 0; k < 4; ++k) {
        const int m = lane + 32 * k;
        float acc = 0.f;
#pragma unroll
        for (int j = 0; j < LD_; ++j)
            acc = fmaf(low[j], s_mb[j * MEM_ + m], acc);
        f1[k] = acc * scale;
    }

    float mx = fmaxf(fmaxf(f1[0], f1[1]), fmaxf(f1[2], f1[3]));
#pragma unroll
    for (int off = 16; off > 0; off >>= 1)
        mx = fmaxf(mx, __shfl_xor_sync(0xffffffffu, mx, off));
    float e[4], sum = 0.f;
#pragma unroll
    for (int k = 0; k < 4; ++k) { e[k] = expf(f1[k] - mx); sum += e[k]; }
#pragma unroll
    for (int off = 16; off > 0; off >>= 1)
        sum += __shfl_xor_sync(0xffffffffu, sum, off);
    const float inv = 1.0f / sum;

    float y1[LD_];
#pragma unroll
    for (int j = 0; j < LD_; ++j) {
        float acc = 0.f;
#pragma unroll
        for (int k = 0; k < 4; ++k)
            acc = fmaf(e[k] * inv, s_mb[j * MEM_ + lane + 32 * k], acc);
#pragma unroll
        for (int off = 16; off > 0; off >>= 1)
            acc += __shfl_xor_sync(0xffffffffu, acc, off);
        y1[j] = acc;
    }

#pragma unroll
    for (int k = 0; k < 2; ++k) {
        const int c = lane + 32 * k;
        float acc = s_bup[c];
#pragma unroll
        for (int j = 0; j < LD_; ++j)
            acc = fmaf(y1[j], s_wup[j * C_ + c], acc);
        const float g = 1.0f / (1.0f + expf(-acc));
        g_gateT[(size_t)(b * C_ + c) * W_ + w] = g * muv;
    }
}

// ---------------------------------------------------------------------------
// Kernel 3: out = x * gate. Fixed float4 column per thread (gate is one reg).
// Batch-4 loads (not 8) + __launch_bounds__(256, 6): regs ~66 -> ~40, so 6
// blocks/SM instead of 3 (occ 32% -> ~75%), waves 4.6 -> 2.3.
// ---------------------------------------------------------------------------
__global__ __launch_bounds__(256, 6) void apply_gate_kernel(
    const float* __restrict__ x, float* __restrict__ out)
{
    const int bcq = (NBLK_ - 1) - blockIdx.x;   // reverse order (minor L2 win)
    const int bc  = bcq >> 2;
    const int q   = bcq & (NQ_ - 1);

    const int t   = threadIdx.x;
    const int w4  = t & 63;                     // fixed float4 column
    const int hs  = t >> 6;                     // base h-subrow 0..3

    const float4 gv = __ldg(&((const float4*)(g_gateT + (size_t)bc * W_))[w4]);

    const size_t base = (size_t)bc * (H_ * W_) + (size_t)q * HCHUNK_ * W_;
    const float4* __restrict__ xp = (const float4*)(x + base);
    float4*       __restrict__ op = (float4*)(out + base);

#pragma unroll
    for (int quarter = 0; quarter < 4; ++quarter) {
        float4 v[4];
#pragma unroll
        for (int k = 0; k < 4; ++k)
            v[k] = __ldcs(&xp[(size_t)(hs + 4 * (quarter * 4 + k)) * (W_ / 4) + w4]);
#pragma unroll
        for (int k = 0; k < 4; ++k) {
            v[k].x *= gv.x; v[k].y *= gv.y; v[k].z *= gv.z; v[k].w *= gv.w;
            __stcs(&op[(size_t)(hs + 4 * (quarter * 4 + k)) * (W_ / 4) + w4], v[k]);
        }
    }
}

extern "C" void kernel_launch(void* const* d_in, const int* in_sizes, int n_in,
                              void* d_out, int out_size) {
    const float* x     = (const float*)d_in[0];
    const float* w_sub = (const float*)d_in[1];
    const float* b_sub = (const float*)d_in[2];
    const float* w_up  = (const float*)d_in[3];
    const float* b_up  = (const float*)d_in[4];
    const float* mb    = (const float*)d_in[5];
    const float* mu    = (const float*)d_in[6];
    float* out = (float*)d_out;

    reduce_h_partial_kernel<<<NBLK_, 256>>>(x);
    gate_kernel<<<NROWS_ / 8, 256>>>(w_sub, b_sub, w_up, b_up, mb, mu);
    apply_gate_kernel<<<NBLK_, 256>>>(x, out);
}